// round 15
// baseline (speedup 1.0000x reference)
#include <cuda_runtime.h>
#include <cuda_fp16.h>
#include <cstdint>

// Problem constants (fixed shapes)
#define NNODES 100000
#define NEDGES 3200000
#define C 128           // feature dim (in = hid = out = 128)
#define CAP 128         // fixed CSR row capacity (Poisson(32) in-degree; P(deg>=128)<1e-60)
#define ROW_SPLIT (391 * 128)   // 50048: SpMM1/GEMM2 pipeline split

// ---------------- scratch (static device globals; no allocation) ----------------
// Cleanliness invariant: g_cnt must be all-zero at entry. Zero-init at module
// load; dinv_deg_kernel re-zeroes it every call after consuming it.
__device__ int    g_csr[(size_t)NNODES * CAP];  // fixed-stride CSR (51.2 MB)
__device__ int    g_cnt[NNODES];
__device__ int    g_deg[NNODES];
__device__ float  g_dinv[NNODES];
__device__ __align__(16) __half g_wt1[C * C];   // W1^T fp16 (n-major)
__device__ __align__(16) __half g_wt2[C * C];   // W2^T fp16 (n-major)
__device__ __align__(16) __half g_h[(size_t)NNODES * C];    // GEMM out, fp16
__device__ __align__(16) __half g_buf[(size_t)NNODES * C];  // layer-1 agg+relu out, fp16

// dynamic shared memory for the tensor-core GEMM:
//   Xs  : 128 rows x 136 halves (padded: 272B row stride -> conflict-free ldmatrix)
//   Wts : 128 rows x 136 halves
extern __shared__ __align__(16) __half g_smem[];
#define XS_STRIDE 136
#define WTS_OFF   (128 * XS_STRIDE)
#define GEMM_SMEM_BYTES (2 * 128 * XS_STRIDE * (int)sizeof(__half))

// ---------------- mma helpers ----------------
__device__ __forceinline__ unsigned sptr(const void* p) {
    return (unsigned)__cvta_generic_to_shared(p);
}
__device__ __forceinline__ void ldsm_x4(unsigned& r0, unsigned& r1,
                                        unsigned& r2, unsigned& r3, unsigned addr) {
    asm volatile("ldmatrix.sync.aligned.m8n8.x4.shared.b16 {%0,%1,%2,%3}, [%4];"
                 : "=r"(r0), "=r"(r1), "=r"(r2), "=r"(r3) : "r"(addr));
}
__device__ __forceinline__ void mma16816(float& d0, float& d1, float& d2, float& d3,
                                         unsigned a0, unsigned a1, unsigned a2, unsigned a3,
                                         unsigned b0, unsigned b1) {
    asm volatile(
        "mma.sync.aligned.m16n8k16.row.col.f32.f16.f16.f32 "
        "{%0,%1,%2,%3},{%4,%5,%6,%7},{%8,%9},{%0,%1,%2,%3};"
        : "+f"(d0), "+f"(d1), "+f"(d2), "+f"(d3)
        : "r"(a0), "r"(a1), "r"(a2), "r"(a3), "r"(b0), "r"(b1));
}

// ---------------- prologue kernels ----------------

// one-pass CSR build: rank via atomic, direct scatter into fixed-stride rows.
__global__ void hist_scatter_kernel(const int* __restrict__ ei, int nedges) {
    int t = blockIdx.x * blockDim.x + threadIdx.x;
    int e = t * 4;
    if (e + 4 <= nedges) {
        int4 s4 = *(const int4*)&ei[e];
        int4 d4 = *(const int4*)&ei[nedges + e];
        int r;
        r = atomicAdd(&g_cnt[d4.x], 1); if (r < CAP) g_csr[((size_t)d4.x << 7) + r] = s4.x;
        r = atomicAdd(&g_cnt[d4.y], 1); if (r < CAP) g_csr[((size_t)d4.y << 7) + r] = s4.y;
        r = atomicAdd(&g_cnt[d4.z], 1); if (r < CAP) g_csr[((size_t)d4.z << 7) + r] = s4.z;
        r = atomicAdd(&g_cnt[d4.w], 1); if (r < CAP) g_csr[((size_t)d4.w << 7) + r] = s4.w;
    } else {
        for (int k = e; k < nedges; k++) {
            int d = ei[nedges + k];
            int r = atomicAdd(&g_cnt[d], 1);
            if (r < CAP) g_csr[((size_t)d << 7) + r] = ei[k];
        }
    }
}

// W1, W2 (fp32 [k][n]) -> g_wt1, g_wt2 (fp16 [n][k]); one launch, 128 blocks.
__global__ void wt_kernel(const float* __restrict__ W1, const float* __restrict__ W2) {
    int i = blockIdx.x * blockDim.x + threadIdx.x;   // 32768 threads
    const float* W = (i < 16384) ? W1 : W2;
    __half* dst = (i < 16384) ? g_wt1 : g_wt2;
    int j = i & 16383;
    int k = j >> 7, n = j & 127;                     // coalesced read
    dst[n * C + k] = __float2half(W[j]);
}

// tiny: dinv = rsqrt(cnt+1), deg = cnt, cnt = 0 (self-clean). 100k elems, ~2us.
__global__ void dinv_deg_kernel(int n) {
    int i = blockIdx.x * blockDim.x + threadIdx.x;
    if (i >= n) return;
    int c = g_cnt[i];
    g_dinv[i] = rsqrtf((float)(c + 1));
    g_deg[i] = c;
    g_cnt[i] = 0;   // self-clean for next call
}

// ---------------- GEMM (tensor core): g_h(fp16) = [dinv ⊙] (X @ W) ------------
// Block: 128 rows x 128 cols, K=128 resident. 8 warps: 4 (m) x 2 (n).
// LAYER=1: UNSCALED (dinv[s] applied as gather weight in SpMM1).
// LAYER=2: dinv folded in epilogue (dinv ready long before).
template <int LAYER>
__global__ __launch_bounds__(256) void gemm_tc_kernel(
    const float* __restrict__ Xin, int blk0, int nrows) {
    __half* Xs  = g_smem;            // [128][136]
    __half* Wts = g_smem + WTS_OFF;  // [128][136]  (W^T: [n][k])
    const __half* __restrict__ Wg = (LAYER == 1) ? g_wt1 : g_wt2;
    const int tid  = threadIdx.x;
    const int lane = tid & 31;
    const int wid  = tid >> 5;
    const int row_blk = (blockIdx.x + blk0) * 128;

    // load W^T (fp16, 128x128 halves = 2048 uint4)
    #pragma unroll
    for (int i = tid; i < 2048; i += 256) {
        int r = i >> 4, j = i & 15;
        *(uint4*)&Wts[r * XS_STRIDE + j * 8] = ((const uint4*)Wg)[i];
    }
    // X rows into Xs
    if (LAYER == 1) {
        #pragma unroll
        for (int i = tid; i < 4096; i += 256) {       // 128 rows x 32 float4
            int r = i >> 5, j = i & 31;
            int gr = row_blk + r;
            float4 v = (gr < nrows) ? ((const float4*)&Xin[(size_t)gr * C])[j]
                                    : make_float4(0.f, 0.f, 0.f, 0.f);
            __half2 h0 = __floats2half2_rn(v.x, v.y);
            __half2 h1 = __floats2half2_rn(v.z, v.w);
            uint2 st;
            st.x = *(unsigned*)&h0;
            st.y = *(unsigned*)&h1;
            *(uint2*)&Xs[r * XS_STRIDE + j * 4] = st;
        }
    } else {
        #pragma unroll
        for (int i = tid; i < 2048; i += 256) {       // 128 rows x 16 uint4 (fp16)
            int r = i >> 4, j = i & 15;
            int gr = row_blk + r;
            uint4 v = (gr < nrows) ? *(const uint4*)&g_buf[(size_t)gr * C + j * 8]
                                   : make_uint4(0u, 0u, 0u, 0u);
            *(uint4*)&Xs[r * XS_STRIDE + j * 8] = v;
        }
    }
    __syncthreads();

    const int warp_m = wid & 3;        // 4 m-warps -> 32 rows each
    const int warp_n = wid >> 2;       // 2 n-warps -> 64 cols each
    const int m0 = warp_m * 32;
    const int n0 = warp_n * 64;

    float acc[2][8][4];
    #pragma unroll
    for (int mt = 0; mt < 2; mt++)
        #pragma unroll
        for (int nt = 0; nt < 8; nt++)
            #pragma unroll
            for (int q = 0; q < 4; q++) acc[mt][nt][q] = 0.f;

    #pragma unroll
    for (int ks = 0; ks < 8; ks++) {
        const int k0 = ks * 16;
        unsigned A0[4], A1[4];
        {
            const __half* p0 = &Xs[(m0 + 0 + (lane & 15)) * XS_STRIDE + k0 + (lane >> 4) * 8];
            ldsm_x4(A0[0], A0[1], A0[2], A0[3], sptr(p0));
            const __half* p1 = &Xs[(m0 + 16 + (lane & 15)) * XS_STRIDE + k0 + (lane >> 4) * 8];
            ldsm_x4(A1[0], A1[1], A1[2], A1[3], sptr(p1));
        }
        // B: Wts is [n][k] row-major == ".col" B operand -> NON-trans ldmatrix
        unsigned Bf[8][2];
        #pragma unroll
        for (int np = 0; np < 4; np++) {
            int g = lane >> 3;
            const __half* p = &Wts[(n0 + np * 16 + (g >> 1) * 8 + (lane & 7)) * XS_STRIDE
                                   + k0 + (g & 1) * 8];
            unsigned t0, t1, t2, t3;
            ldsm_x4(t0, t1, t2, t3, sptr(p));
            Bf[2 * np + 0][0] = t0; Bf[2 * np + 0][1] = t1;
            Bf[2 * np + 1][0] = t2; Bf[2 * np + 1][1] = t3;
        }
        #pragma unroll
        for (int nt = 0; nt < 8; nt++) {
            mma16816(acc[0][nt][0], acc[0][nt][1], acc[0][nt][2], acc[0][nt][3],
                     A0[0], A0[1], A0[2], A0[3], Bf[nt][0], Bf[nt][1]);
            mma16816(acc[1][nt][0], acc[1][nt][1], acc[1][nt][2], acc[1][nt][3],
                     A1[0], A1[1], A1[2], A1[3], Bf[nt][0], Bf[nt][1]);
        }
    }

    // epilogue: (LAYER==2 only) scale row by dinv; store fp16
    #pragma unroll
    for (int mt = 0; mt < 2; mt++) {
        int r0 = row_blk + m0 + mt * 16 + (lane >> 2);
        int r1 = r0 + 8;
        float di0 = 1.f, di1 = 1.f;
        if (LAYER == 2) {
            di0 = (r0 < nrows) ? g_dinv[r0] : 0.f;
            di1 = (r1 < nrows) ? g_dinv[r1] : 0.f;
        }
        #pragma unroll
        for (int nt = 0; nt < 8; nt++) {
            int col = n0 + nt * 8 + (lane & 3) * 2;
            if (r0 < nrows) {
                __half2 h = __floats2half2_rn(acc[mt][nt][0] * di0, acc[mt][nt][1] * di0);
                *(unsigned*)&g_h[(size_t)r0 * C + col] = *(unsigned*)&h;
            }
            if (r1 < nrows) {
                __half2 h = __floats2half2_rn(acc[mt][nt][2] * di1, acc[mt][nt][3] * di1);
                *(unsigned*)&g_h[(size_t)r1 * C + col] = *(unsigned*)&h;
            }
        }
    }
}

// ---------------- SpMM: warp-per-destination-row, fixed-stride CSR ------------
// LAYER=1: out[d] = dinv[d]*( sum dinv[s]*h[s] + dinv[d]*h[d] ) + b  -> relu -> g_buf fp16
//          (h unscaled; dinv[s] loaded per edge — independent uniform load, L2-hot 400KB)
// LAYER=2: out[d] = dinv[d]*( sum h'[s] + h'[d] ) + b                -> fp32 out
//          (h' prescaled by GEMM2 epilogue)
template <int LAYER>
__global__ __launch_bounds__(256) void spmm_kernel(
    const float* __restrict__ bias, float* __restrict__ outp, int row0, int row1) {
    int warp = row0 + ((blockIdx.x * blockDim.x + threadIdx.x) >> 5);
    int lane = threadIdx.x & 31;
    if (warp >= row1) return;
    const uint2* __restrict__ H2 = (const uint2*)g_h;
    const int* __restrict__ row = &g_csr[(size_t)warp << 7];
    float dd = g_dinv[warp];
    int deg = g_deg[warp];

    float4 acc;
    {
        uint2 raw = __ldcg(&H2[(size_t)warp * 32 + lane]);  // self loop
        float2 f0 = __half22float2(*(const __half2*)&raw.x);
        float2 f1 = __half22float2(*(const __half2*)&raw.y);
        float w0 = (LAYER == 1) ? dd : 1.f;
        acc = make_float4(f0.x * w0, f0.y * w0, f1.x * w0, f1.y * w0);
    }
    int e = 0;
    for (; e + 8 <= deg; e += 8) {
        int s[8];
        #pragma unroll
        for (int j = 0; j < 8; j++) s[j] = row[e + j];
        uint2 r[8];
        float w[8];
        #pragma unroll
        for (int j = 0; j < 8; j++) {
            if (LAYER == 1) w[j] = g_dinv[s[j]];
            r[j] = __ldcg(&H2[(size_t)s[j] * 32 + lane]);
        }
        #pragma unroll
        for (int j = 0; j < 8; j++) {
            float2 f0 = __half22float2(*(const __half2*)&r[j].x);
            float2 f1 = __half22float2(*(const __half2*)&r[j].y);
            if (LAYER == 1) {
                acc.x += f0.x * w[j]; acc.y += f0.y * w[j];
                acc.z += f1.x * w[j]; acc.w += f1.y * w[j];
            } else {
                acc.x += f0.x; acc.y += f0.y; acc.z += f1.x; acc.w += f1.y;
            }
        }
    }
    for (; e < deg; e++) {
        int s = row[e];
        float w = (LAYER == 1) ? g_dinv[s] : 1.f;
        uint2 raw = __ldcg(&H2[(size_t)s * 32 + lane]);
        float2 f0 = __half22float2(*(const __half2*)&raw.x);
        float2 f1 = __half22float2(*(const __half2*)&raw.y);
        acc.x += f0.x * w; acc.y += f0.y * w; acc.z += f1.x * w; acc.w += f1.y * w;
    }
    float4 b = ((const float4*)bias)[lane];
    acc.x = acc.x * dd + b.x;
    acc.y = acc.y * dd + b.y;
    acc.z = acc.z * dd + b.z;
    acc.w = acc.w * dd + b.w;
    if (LAYER == 1) {
        acc.x = fmaxf(acc.x, 0.f);
        acc.y = fmaxf(acc.y, 0.f);
        acc.z = fmaxf(acc.z, 0.f);
        acc.w = fmaxf(acc.w, 0.f);
        __half2 h0 = __floats2half2_rn(acc.x, acc.y);
        __half2 h1 = __floats2half2_rn(acc.z, acc.w);
        uint2 st;
        st.x = *(unsigned*)&h0;
        st.y = *(unsigned*)&h1;
        ((uint2*)g_buf)[(size_t)warp * 32 + lane] = st;
    } else {
        ((float4*)outp)[(size_t)warp * 32 + lane] = acc;
    }
}

// ---------------- launch (fork/join graph with aux stream) ----------------
static inline int spmm_grid(int rows) { return (rows * 32 + 255) / 256; }

extern "C" void kernel_launch(void* const* d_in, const int* in_sizes, int n_in,
                              void* d_out, int out_size) {
    const float* x  = (const float*)d_in[0];
    const int*   ei = (const int*)d_in[1];     // int32 edge index (2 x E)
    const float* W1 = (const float*)d_in[2];
    const float* b1 = (const float*)d_in[3];
    const float* W2 = (const float*)d_in[4];
    const float* b2 = (const float*)d_in[5];
    float* out = (float*)d_out;

    const int nedges = in_sizes[1] / 2;   // 3,200,000
    const int n = NNODES;

    cudaFuncSetAttribute(gemm_tc_kernel<1>,
                         cudaFuncAttributeMaxDynamicSharedMemorySize, GEMM_SMEM_BYTES);
    cudaFuncSetAttribute(gemm_tc_kernel<2>,
                         cudaFuncAttributeMaxDynamicSharedMemorySize, GEMM_SMEM_BYTES);

    // aux stream + events (host objects; created during the capture call, never
    // destroyed -> become parallel branches of the captured graph)
    cudaStream_t sA;
    cudaStreamCreateWithFlags(&sA, cudaStreamNonBlocking);
    cudaEvent_t evFork, evG1, evS1lo, evS1hi, evG2;
    cudaEventCreateWithFlags(&evFork, cudaEventDisableTiming);
    cudaEventCreateWithFlags(&evG1,   cudaEventDisableTiming);
    cudaEventCreateWithFlags(&evS1lo, cudaEventDisableTiming);
    cudaEventCreateWithFlags(&evS1hi, cudaEventDisableTiming);
    cudaEventCreateWithFlags(&evG2,   cudaEventDisableTiming);

    // fork aux branch at t=0: wt + UNSCALED GEMM1 (no edge-prologue dependency)
    cudaEventRecord(evFork, 0);
    cudaStreamWaitEvent(sA, evFork, 0);
    wt_kernel<<<128, 256, 0, sA>>>(W1, W2);
    gemm_tc_kernel<1><<<782, 256, GEMM_SMEM_BYTES, sA>>>(x, 0, n);  // || hist_scatter
    cudaEventRecord(evG1, sA);

    // main branch: one-pass CSR build + tiny dinv/deg
    hist_scatter_kernel<<<(nedges / 4 + 255) / 256, 256>>>(ei, nedges);
    dinv_deg_kernel<<<(n + 255) / 256, 256>>>(n);

    // main: SpMM1 (needs csr+dinv from main order, g_h from evG1),
    // split at ROW_SPLIT so GEMM2_lo can start early on aux
    cudaStreamWaitEvent(0, evG1, 0);
    spmm_kernel<1><<<spmm_grid(ROW_SPLIT), 256>>>(b1, nullptr, 0, ROW_SPLIT);
    cudaEventRecord(evS1lo, 0);
    spmm_kernel<1><<<spmm_grid(n - ROW_SPLIT), 256>>>(b1, nullptr, ROW_SPLIT, n);
    cudaEventRecord(evS1hi, 0);

    // aux: GEMM2 halves (row-block-local in g_buf; dinv ready via evS1lo order)
    cudaStreamWaitEvent(sA, evS1lo, 0);
    gemm_tc_kernel<2><<<391, 256, GEMM_SMEM_BYTES, sA>>>(nullptr, 0, n);
    cudaStreamWaitEvent(sA, evS1hi, 0);
    gemm_tc_kernel<2><<<391, 256, GEMM_SMEM_BYTES, sA>>>(nullptr, 391, n);
    cudaEventRecord(evG2, sA);

    // main: final SpMM (needs all of g_h)
    cudaStreamWaitEvent(0, evG2, 0);
    spmm_kernel<2><<<spmm_grid(n), 256>>>(b2, out, 0, n);
}